// round 11
// baseline (speedup 1.0000x reference)
#include <cuda_runtime.h>
#include <cuda_bf16.h>
#include <cstdint>

#define BATCH  4096
#define NREL   128
#define EMB    256
#define KDIM   512
#define NSEG   8          // 8 segments of 64 source floats; pair [x^2_seg, x_seg]

// ---------------- device globals ----------------
// B pre-packed: [2 ntiles][8 segs][ w2-tile 8K | w1-tile 8K ]  (256 KB)
__device__ __align__(128) __nv_bfloat16 g_Bs[NREL * 1024];
__device__ __align__(16) float g_const[NREL];

// ---------------- helpers ----------------
__device__ __forceinline__ uint32_t smem_u32(const void* p) {
    uint32_t a;
    asm("{ .reg .u64 t; cvta.to.shared.u64 t, %1; cvt.u32.u64 %0, t; }" : "=r"(a) : "l"(p));
    return a;
}
__device__ __forceinline__ void ldsm_x4(uint32_t& r0, uint32_t& r1, uint32_t& r2, uint32_t& r3,
                                        uint32_t addr) {
    asm volatile("ldmatrix.sync.aligned.m8n8.x4.shared.b16 {%0,%1,%2,%3}, [%4];"
                 : "=r"(r0), "=r"(r1), "=r"(r2), "=r"(r3) : "r"(addr));
}
__device__ __forceinline__ void mma16816(float* d, const uint32_t* a, uint32_t b0, uint32_t b1) {
    asm volatile(
        "mma.sync.aligned.m16n8k16.row.col.f32.bf16.bf16.f32 "
        "{%0,%1,%2,%3}, {%4,%5,%6,%7}, {%8,%9}, {%0,%1,%2,%3};"
        : "+f"(d[0]), "+f"(d[1]), "+f"(d[2]), "+f"(d[3])
        : "r"(a[0]), "r"(a[1]), "r"(a[2]), "r"(a[3]), "r"(b0), "r"(b1));
}
#define MBAR_INIT(addr, cnt) \
    asm volatile("mbarrier.init.shared.b64 [%0], %1;" :: "r"(addr), "r"((uint32_t)(cnt)) : "memory")
#define MBAR_EXPECT_TX(addr, bytes) \
    asm volatile("mbarrier.arrive.expect_tx.shared.b64 _, [%0], %1;" :: "r"(addr), "r"((uint32_t)(bytes)) : "memory")
#define MBAR_WAIT(addr, par) do { \
    uint32_t _m = (addr); uint32_t _p = (par); uint32_t _d; \
    asm volatile("{\n\t.reg .pred p;\n\tmbarrier.try_wait.parity.acquire.cta.shared::cta.b64 p, [%1], %2;\n\tselp.b32 %0, 1, 0, p;\n\t}" \
        : "=r"(_d) : "r"(_m), "r"(_p) : "memory"); \
    if (!_d) { \
        asm volatile("{\n\t.reg .pred P1;\n\tWL_%=: \n\tmbarrier.try_wait.parity.acquire.cta.shared::cta.b64 P1, [%0], %1, 0x989680;\n\t@P1 bra.uni WD_%=;\n\tbra.uni WL_%=;\n\tWD_%=: \n\t}" \
            :: "r"(_m), "r"(_p) : "memory"); \
    } } while (0)
#define CP_BULK(dst, src, sz, mbar) \
    asm volatile("cp.async.bulk.shared::cta.global.mbarrier::complete_tx::bytes [%0], [%1], %2, [%3];" \
        :: "r"(dst), "l"(src), "r"((uint32_t)(sz)), "r"(mbar) : "memory")

#define SWZ(bo) ((bo) ^ (((bo) >> 3) & 0x70))

// ---------------- prep: pack B + const (one block per relation) ----------------
// Pack order: [ntile][seg][w2 8K | w1 8K], tiles 64 rows x 128B swizzled.
__global__ void prep_B(const float* __restrict__ mus,
                       const float* __restrict__ sigmas,
                       const float* __restrict__ priors) {
    const int r = blockIdx.x;          // 0..127
    const int t = threadIdx.x;         // 0..255
    const int nt  = r >> 6;            // ntile
    const int rin = r & 63;
    char* base = reinterpret_cast<char*>(g_Bs) + (size_t)nt * 8 * 16384;

    float part = 0.0f;
    #pragma unroll
    for (int i = 0; i < 2; i++) {
        const int k = t + i * 256;     // 0..511
        const float s    = sigmas[r * KDIM + k];
        const float mu   = mus[r * KDIM + k];
        const float inv2 = 1.0f / (s * s);
        const int seg = k >> 6;
        const uint32_t off = SWZ((uint32_t)(rin * 128 + (k & 63) * 2));
        *reinterpret_cast<__nv_bfloat16*>(base + (size_t)seg * 16384 + off)
            = __float2bfloat16(-0.5f * inv2);        // w2 <-> x^2
        *reinterpret_cast<__nv_bfloat16*>(base + (size_t)seg * 16384 + 8192 + off)
            = __float2bfloat16(mu * inv2);           // w1 <-> x
        part += -0.5f * mu * mu * inv2 - logf(s) - 0.9189385332046727f;
    }

    __shared__ float red[8];
    #pragma unroll
    for (int off = 16; off > 0; off >>= 1)
        part += __shfl_down_sync(0xffffffffu, part, off);
    if ((t & 31) == 0) red[t >> 5] = part;
    __syncthreads();
    if (t < 8) {
        float v = red[t];
        #pragma unroll
        for (int off = 4; off > 0; off >>= 1)
            v += __shfl_down_sync(0x000000ffu, v, off);
        if (t == 0) g_const[r] = v + priors[r] * (float)KDIM;
    }
}

// ---------------- main ----------------
// CTA tile 32(m) x 64(n), 256 threads. EVERYTHING resident:
//   A: [8 segs][x^2 4K | x 4K] = 64 KB (direct load, once)
//   B: [8 segs][w2 8K | w1 8K] = 128 KB (8 bulk copies, 8 mbarriers)
// Main loop: per-seg MBAR_WAIT only — no __syncthreads, no stage reuse.
#define SMB_OFF     65536
#define MBAR_OFF    (SMB_OFF + NSEG * 16384)
#define SMEM_TOTAL  (MBAR_OFF + 64)

__global__ __launch_bounds__(256)
void nb_mma(const float* __restrict__ sbjs,
            const float* __restrict__ objs,
            float* __restrict__ out) {
    extern __shared__ char smem[];
    const uint32_t sb = smem_u32(smem);

    const int tid  = threadIdx.x;
    const int lane = tid & 31;
    const int wid  = tid >> 5;              // 0..7
    const int mtile = blockIdx.x >> 1;      // 0..127
    const int ntile = blockIdx.x & 1;       // 0..1

    if (tid == 0) {
        #pragma unroll
        for (int s = 0; s < NSEG; s++) MBAR_INIT(sb + MBAR_OFF + s * 8, 1);
    }
    __syncthreads();

    // ---- issue ALL B segments up front (bulk engine, independent mbarriers) ----
    if (tid == 0) {
        const char* bSrc = reinterpret_cast<const char*>(g_Bs) + (size_t)ntile * 8 * 16384;
        #pragma unroll
        for (int s = 0; s < NSEG; s++) {
            const uint32_t mb = sb + MBAR_OFF + s * 8;
            MBAR_EXPECT_TX(mb, 16384);
            CP_BULK(sb + SMB_OFF + s * 16384, bSrc + (size_t)s * 16384, 16384, mb);
        }
    }

    // ---- A full preload: 8 consecutive floats per thread per segment ----
    {
        const int arow = tid >> 3;               // 0..31
        const int kq   = (tid & 7) * 8;          // 0..56
        const uint32_t aOff = SWZ((uint32_t)(arow * 128 + kq * 2));
        const float* srcS = sbjs + (size_t)(mtile * 32 + arow) * EMB + kq;
        const float* srcO = objs + (size_t)(mtile * 32 + arow) * EMB + kq;
        #pragma unroll
        for (int h = 0; h < 2; h++) {            // h=0: segs 0-3 (sbjs), h=1: segs 4-7 (objs)
            const float* src = h ? srcO : srcS;
            float4 v[8];
            #pragma unroll
            for (int s = 0; s < 4; s++) {
                v[2*s]   = reinterpret_cast<const float4*>(src + s * 64)[0];
                v[2*s+1] = reinterpret_cast<const float4*>(src + s * 64)[1];
            }
            #pragma unroll
            for (int s = 0; s < 4; s++) {
                const float4 v0 = v[2*s], v1 = v[2*s+1];
                __nv_bfloat162 q0 = __floats2bfloat162_rn(v0.x * v0.x, v0.y * v0.y);
                __nv_bfloat162 q1 = __floats2bfloat162_rn(v0.z * v0.z, v0.w * v0.w);
                __nv_bfloat162 q2 = __floats2bfloat162_rn(v1.x * v1.x, v1.y * v1.y);
                __nv_bfloat162 q3 = __floats2bfloat162_rn(v1.z * v1.z, v1.w * v1.w);
                __nv_bfloat162 r0 = __floats2bfloat162_rn(v0.x, v0.y);
                __nv_bfloat162 r1 = __floats2bfloat162_rn(v0.z, v0.w);
                __nv_bfloat162 r2 = __floats2bfloat162_rn(v1.x, v1.y);
                __nv_bfloat162 r3 = __floats2bfloat162_rn(v1.z, v1.w);
                uint4 uq, ur;
                uq.x = *reinterpret_cast<uint32_t*>(&q0); uq.y = *reinterpret_cast<uint32_t*>(&q1);
                uq.z = *reinterpret_cast<uint32_t*>(&q2); uq.w = *reinterpret_cast<uint32_t*>(&q3);
                ur.x = *reinterpret_cast<uint32_t*>(&r0); ur.y = *reinterpret_cast<uint32_t*>(&r1);
                ur.z = *reinterpret_cast<uint32_t*>(&r2); ur.w = *reinterpret_cast<uint32_t*>(&r3);
                char* dst = smem + (size_t)(h * 4 + s) * 8192;
                *reinterpret_cast<uint4*>(dst + aOff)        = uq;   // x^2 tile
                *reinterpret_cast<uint4*>(dst + 4096 + aOff) = ur;   // x tile
            }
        }
    }

    // ---- compute mappings: 8 warps as 2(m) x 4(n), warp tile 16x16 ----
    const int wm = wid & 1;
    const int wn = wid >> 1;
    const int mrow = wm * 16 + (lane & 15);
    const uint32_t aLdRow = (uint32_t)(mrow * 128);
    const uint32_t aLdXor = (uint32_t)((mrow & 7) << 4);
    const uint32_t aLdBlk = (uint32_t)((lane >> 4) * 16);

    const int nrow = wn * 16 + ((lane >> 4) * 8) + (lane & 7);
    const uint32_t bLdRow = (uint32_t)(nrow * 128);
    const uint32_t bLdXor = (uint32_t)((nrow & 7) << 4);
    const uint32_t bLdBlk = (uint32_t)(((lane >> 3) & 1) * 16);

    float acc[2][4];
    #pragma unroll
    for (int i = 0; i < 2; i++)
        #pragma unroll
        for (int j = 0; j < 4; j++) acc[i][j] = 0.0f;

    __syncthreads();   // A resident for all warps (the ONLY block barrier before epilogue)

    // ---- main loop: no __syncthreads, B segments arrive in order ----
    for (int seg = 0; seg < NSEG; seg++) {
        MBAR_WAIT(sb + MBAR_OFF + seg * 8, 0);
        const uint32_t aStage = sb + (uint32_t)seg * 8192;
        const uint32_t bStage = sb + SMB_OFF + (uint32_t)seg * 16384;
        #pragma unroll
        for (int kc = 0; kc < 2; kc++) {            // kc=0: x^2*w2, kc=1: x*w1
            const uint32_t aB = aStage + kc * 4096;
            const uint32_t bB = bStage + kc * 8192;
            #pragma unroll
            for (int ks = 0; ks < 4; ks++) {
                const uint32_t kcol = (uint32_t)(ks * 32);
                uint32_t a[4];
                ldsm_x4(a[0], a[1], a[2], a[3], aB + aLdRow + ((kcol + aLdBlk) ^ aLdXor));
                uint32_t b[4];
                ldsm_x4(b[0], b[1], b[2], b[3], bB + bLdRow + ((kcol + bLdBlk) ^ bLdXor));
                mma16816(acc[0], a, b[0], b[1]);
                mma16816(acc[1], a, b[2], b[3]);
            }
        }
    }

    // ---- epilogue ----
    #pragma unroll
    for (int nf = 0; nf < 2; nf++) {
        const int n0 = ntile * 64 + wn * 16 + nf * 8 + (lane & 3) * 2;
        const float c0 = g_const[n0], c1 = g_const[n0 + 1];
        const int r0 = mtile * 32 + wm * 16 + (lane >> 2);
        float2 o0, o1;
        o0.x = acc[nf][0] + c0; o0.y = acc[nf][1] + c1;
        o1.x = acc[nf][2] + c0; o1.y = acc[nf][3] + c1;
        *reinterpret_cast<float2*>(&out[(size_t)r0 * NREL + n0])       = o0;
        *reinterpret_cast<float2*>(&out[(size_t)(r0 + 8) * NREL + n0]) = o1;
    }
}

extern "C" void kernel_launch(void* const* d_in, const int* in_sizes, int n_in,
                              void* d_out, int out_size) {
    const float* sbjs   = (const float*)d_in[0];
    const float* objs   = (const float*)d_in[1];
    const float* mus    = (const float*)d_in[2];
    const float* sigmas = (const float*)d_in[3];
    const float* priors = (const float*)d_in[4];
    float* out = (float*)d_out;

    cudaFuncSetAttribute(nb_mma, cudaFuncAttributeMaxDynamicSharedMemorySize, SMEM_TOTAL);

    prep_B<<<NREL, 256>>>(mus, sigmas, priors);
    nb_mma<<<256, 256, SMEM_TOTAL>>>(sbjs, objs, out);
    (void)in_sizes; (void)n_in; (void)out_size;
}

// round 12
// speedup vs baseline: 1.1210x; 1.1210x over previous
#include <cuda_runtime.h>
#include <cuda_bf16.h>
#include <cstdint>

#define BATCH  4096
#define NREL   128
#define EMB    256
#define KDIM   512
#define NSEG   8          // 8 segments of 64 source floats; pair [x^2_seg, x_seg]

// ---------------- device globals ----------------
// B pre-packed: [2 ntiles][8 segs][ w2-tile 8K | w1-tile 8K ]  (256 KB)
__device__ __align__(128) __nv_bfloat16 g_Bs[NREL * 1024];
__device__ __align__(16) float g_const[NREL];

// ---------------- helpers ----------------
__device__ __forceinline__ uint32_t smem_u32(const void* p) {
    uint32_t a;
    asm("{ .reg .u64 t; cvta.to.shared.u64 t, %1; cvt.u32.u64 %0, t; }" : "=r"(a) : "l"(p));
    return a;
}
__device__ __forceinline__ void ldsm_x4(uint32_t& r0, uint32_t& r1, uint32_t& r2, uint32_t& r3,
                                        uint32_t addr) {
    asm volatile("ldmatrix.sync.aligned.m8n8.x4.shared.b16 {%0,%1,%2,%3}, [%4];"
                 : "=r"(r0), "=r"(r1), "=r"(r2), "=r"(r3) : "r"(addr));
}
__device__ __forceinline__ void mma16816(float* d, const uint32_t* a, uint32_t b0, uint32_t b1) {
    asm volatile(
        "mma.sync.aligned.m16n8k16.row.col.f32.bf16.bf16.f32 "
        "{%0,%1,%2,%3}, {%4,%5,%6,%7}, {%8,%9}, {%0,%1,%2,%3};"
        : "+f"(d[0]), "+f"(d[1]), "+f"(d[2]), "+f"(d[3])
        : "r"(a[0]), "r"(a[1]), "r"(a[2]), "r"(a[3]), "r"(b0), "r"(b1));
}
#define MBAR_INIT(addr, cnt) \
    asm volatile("mbarrier.init.shared.b64 [%0], %1;" :: "r"(addr), "r"((uint32_t)(cnt)) : "memory")
#define MBAR_EXPECT_TX(addr, bytes) \
    asm volatile("mbarrier.arrive.expect_tx.shared.b64 _, [%0], %1;" :: "r"(addr), "r"((uint32_t)(bytes)) : "memory")
#define MBAR_WAIT(addr, par) do { \
    uint32_t _m = (addr); uint32_t _p = (par); uint32_t _d; \
    asm volatile("{\n\t.reg .pred p;\n\tmbarrier.try_wait.parity.acquire.cta.shared::cta.b64 p, [%1], %2;\n\tselp.b32 %0, 1, 0, p;\n\t}" \
        : "=r"(_d) : "r"(_m), "r"(_p) : "memory"); \
    if (!_d) { \
        asm volatile("{\n\t.reg .pred P1;\n\tWL_%=: \n\tmbarrier.try_wait.parity.acquire.cta.shared::cta.b64 P1, [%0], %1, 0x989680;\n\t@P1 bra.uni WD_%=;\n\tbra.uni WL_%=;\n\tWD_%=: \n\t}" \
            :: "r"(_m), "r"(_p) : "memory"); \
    } } while (0)
#define CP_BULK(dst, src, sz, mbar) \
    asm volatile("cp.async.bulk.shared::cta.global.mbarrier::complete_tx::bytes [%0], [%1], %2, [%3];" \
        :: "r"(dst), "l"(src), "r"((uint32_t)(sz)), "r"(mbar) : "memory")

#define SWZ(bo) ((bo) ^ (((bo) >> 3) & 0x70))

// ---------------- prep: pack B + const (one block per relation) ----------------
// Pack order: [ntile][seg][w2 8K | w1 8K], tiles 64 rows x 128B swizzled.
__global__ void prep_B(const float* __restrict__ mus,
                       const float* __restrict__ sigmas,
                       const float* __restrict__ priors) {
    const int r = blockIdx.x;          // 0..127
    const int t = threadIdx.x;         // 0..255
    const int nt  = r >> 6;            // ntile
    const int rin = r & 63;
    char* base = reinterpret_cast<char*>(g_Bs) + (size_t)nt * 8 * 16384;

    float part = 0.0f;
    #pragma unroll
    for (int i = 0; i < 2; i++) {
        const int k = t + i * 256;     // 0..511
        const float s    = sigmas[r * KDIM + k];
        const float mu   = mus[r * KDIM + k];
        const float inv2 = 1.0f / (s * s);
        const int seg = k >> 6;
        const uint32_t off = SWZ((uint32_t)(rin * 128 + (k & 63) * 2));
        *reinterpret_cast<__nv_bfloat16*>(base + (size_t)seg * 16384 + off)
            = __float2bfloat16(-0.5f * inv2);        // w2 <-> x^2
        *reinterpret_cast<__nv_bfloat16*>(base + (size_t)seg * 16384 + 8192 + off)
            = __float2bfloat16(mu * inv2);           // w1 <-> x
        part += -0.5f * mu * mu * inv2 - logf(s) - 0.9189385332046727f;
    }

    __shared__ float red[8];
    #pragma unroll
    for (int off = 16; off > 0; off >>= 1)
        part += __shfl_down_sync(0xffffffffu, part, off);
    if ((t & 31) == 0) red[t >> 5] = part;
    __syncthreads();
    if (t < 8) {
        float v = red[t];
        #pragma unroll
        for (int off = 4; off > 0; off >>= 1)
            v += __shfl_down_sync(0x000000ffu, v, off);
        if (t == 0) g_const[r] = v + priors[r] * (float)KDIM;
    }
}

// ---------------- main ----------------
// CTA tile 64(m) x 64(n), 512 threads, grid 128 = ONE wave.
//   A: double buffer [2][x^2 8K | x 8K] = 32 KB (direct LDG->STS per segment)
//   B: FULLY RESIDENT [8 segs][w2 8K | w1 8K] = 128 KB (8 bulk copies up front,
//      8 independent mbarriers -> one fast-path wait per segment, no recycling)
#define SMB_OFF     32768
#define MBAR_OFF    (SMB_OFF + NSEG * 16384)
#define SMEM_TOTAL  (MBAR_OFF + 64)          // 163,904 B

__global__ __launch_bounds__(512)
void nb_mma(const float* __restrict__ sbjs,
            const float* __restrict__ objs,
            float* __restrict__ out) {
    extern __shared__ char smem[];
    const uint32_t sb = smem_u32(smem);

    const int tid  = threadIdx.x;
    const int lane = tid & 31;
    const int wid  = tid >> 5;              // 0..15
    const int mtile = blockIdx.x >> 1;      // 0..63
    const int ntile = blockIdx.x & 1;       // 0..1

    if (tid == 0) {
        #pragma unroll
        for (int s = 0; s < NSEG; s++) MBAR_INIT(sb + MBAR_OFF + s * 8, 1);
    }
    __syncthreads();

    // ---- issue ALL B segments up front ----
    if (tid == 0) {
        const char* bSrc = reinterpret_cast<const char*>(g_Bs) + (size_t)ntile * 8 * 16384;
        #pragma unroll
        for (int s = 0; s < NSEG; s++) {
            const uint32_t mb = sb + MBAR_OFF + s * 8;
            MBAR_EXPECT_TX(mb, 16384);
            CP_BULK(sb + SMB_OFF + s * 16384, bSrc + (size_t)s * 16384, 16384, mb);
        }
    }

    // ---- A loader: 8 consecutive floats per thread per segment (64 rows) ----
    const int arow = tid >> 3;               // 0..63
    const int kq   = (tid & 7) * 8;          // 0..56
    const uint32_t aOff = SWZ((uint32_t)(arow * 128 + kq * 2));
    auto ldgA = [&](int seg, float4& v0, float4& v1) {
        const int kg = seg * 64 + kq;
        const float* src = (kg < EMB)
            ? sbjs + (size_t)(mtile * 64 + arow) * EMB + kg
            : objs + (size_t)(mtile * 64 + arow) * EMB + (kg - EMB);
        v0 = reinterpret_cast<const float4*>(src)[0];
        v1 = reinterpret_cast<const float4*>(src)[1];
    };
    auto stsA = [&](int buf, float4 v0, float4 v1) {
        __nv_bfloat162 q0 = __floats2bfloat162_rn(v0.x * v0.x, v0.y * v0.y);
        __nv_bfloat162 q1 = __floats2bfloat162_rn(v0.z * v0.z, v0.w * v0.w);
        __nv_bfloat162 q2 = __floats2bfloat162_rn(v1.x * v1.x, v1.y * v1.y);
        __nv_bfloat162 q3 = __floats2bfloat162_rn(v1.z * v1.z, v1.w * v1.w);
        __nv_bfloat162 r0 = __floats2bfloat162_rn(v0.x, v0.y);
        __nv_bfloat162 r1 = __floats2bfloat162_rn(v0.z, v0.w);
        __nv_bfloat162 r2 = __floats2bfloat162_rn(v1.x, v1.y);
        __nv_bfloat162 r3 = __floats2bfloat162_rn(v1.z, v1.w);
        uint4 uq, ur;
        uq.x = *reinterpret_cast<uint32_t*>(&q0); uq.y = *reinterpret_cast<uint32_t*>(&q1);
        uq.z = *reinterpret_cast<uint32_t*>(&q2); uq.w = *reinterpret_cast<uint32_t*>(&q3);
        ur.x = *reinterpret_cast<uint32_t*>(&r0); ur.y = *reinterpret_cast<uint32_t*>(&r1);
        ur.z = *reinterpret_cast<uint32_t*>(&r2); ur.w = *reinterpret_cast<uint32_t*>(&r3);
        char* dst = smem + (size_t)buf * 16384;
        *reinterpret_cast<uint4*>(dst + aOff)        = uq;   // x^2 tile (8 KB)
        *reinterpret_cast<uint4*>(dst + 8192 + aOff) = ur;   // x tile   (8 KB)
    };

    // prologue: segment 0 into A buf 0
    {
        float4 v0, v1;
        ldgA(0, v0, v1);
        stsA(0, v0, v1);
    }

    // ---- compute mappings: 16 warps as 4(m) x 4(n), warp tile 16x16 ----
    const int wm = wid & 3;
    const int wn = wid >> 2;
    const int mrow = wm * 16 + (lane & 15);
    const uint32_t aLdRow = (uint32_t)(mrow * 128);
    const uint32_t aLdXor = (uint32_t)((mrow & 7) << 4);
    const uint32_t aLdBlk = (uint32_t)((lane >> 4) * 16);

    const int nrow = wn * 16 + ((lane >> 4) * 8) + (lane & 7);
    const uint32_t bLdRow = (uint32_t)(nrow * 128);
    const uint32_t bLdXor = (uint32_t)((nrow & 7) << 4);
    const uint32_t bLdBlk = (uint32_t)(((lane >> 3) & 1) * 16);

    float acc[2][4];
    #pragma unroll
    for (int i = 0; i < 2; i++)
        #pragma unroll
        for (int j = 0; j < 4; j++) acc[i][j] = 0.0f;

    __syncthreads();   // A buf0 resident

    // ---- main loop: 1 syncthreads + 1 fast-path mbar wait per segment ----
    for (int seg = 0; seg < NSEG; seg++) {
        const int buf = seg & 1;

        // prefetch next A segment BEFORE any waiting (maximize LDG overlap)
        float4 pv0, pv1;
        const bool have_next = (seg + 1 < NSEG);
        if (have_next) ldgA(seg + 1, pv0, pv1);

        MBAR_WAIT(sb + MBAR_OFF + seg * 8, 0);   // B seg resident (fast after ramp)

        const uint32_t aStage = sb + (uint32_t)buf * 16384;
        const uint32_t bStage = sb + SMB_OFF + (uint32_t)seg * 16384;
        #pragma unroll
        for (int kc = 0; kc < 2; kc++) {            // kc=0: x^2*w2, kc=1: x*w1
            const uint32_t aB = aStage + kc * 8192;
            const uint32_t bB = bStage + kc * 8192;
            #pragma unroll
            for (int ks = 0; ks < 4; ks++) {
                const uint32_t kcol = (uint32_t)(ks * 32);
                uint32_t a[4];
                ldsm_x4(a[0], a[1], a[2], a[3], aB + aLdRow + ((kcol + aLdBlk) ^ aLdXor));
                uint32_t b[4];
                ldsm_x4(b[0], b[1], b[2], b[3], bB + bLdRow + ((kcol + bLdBlk) ^ bLdXor));
                mma16816(acc[0], a, b[0], b[1]);
                mma16816(acc[1], a, b[2], b[3]);
            }
        }

        if (have_next) {
            __syncthreads();          // all warps finished reading A[buf^1] (prev seg)
            stsA(buf ^ 1, pv0, pv1);
            __syncthreads();          // A[buf^1] visible for next segment
        }
    }

    // ---- epilogue ----
    #pragma unroll
    for (int nf = 0; nf < 2; nf++) {
        const int n0 = ntile * 64 + wn * 16 + nf * 8 + (lane & 3) * 2;
        const float c0 = g_const[n0], c1 = g_const[n0 + 1];
        const int r0 = mtile * 64 + wm * 16 + (lane >> 2);
        float2 o0, o1;
        o0.x = acc[nf][0] + c0; o0.y = acc[nf][1] + c1;
        o1.x = acc[nf][2] + c0; o1.y = acc[nf][3] + c1;
        *reinterpret_cast<float2*>(&out[(size_t)r0 * NREL + n0])       = o0;
        *reinterpret_cast<float2*>(&out[(size_t)(r0 + 8) * NREL + n0]) = o1;
    }
}

extern "C" void kernel_launch(void* const* d_in, const int* in_sizes, int n_in,
                              void* d_out, int out_size) {
    const float* sbjs   = (const float*)d_in[0];
    const float* objs   = (const float*)d_in[1];
    const float* mus    = (const float*)d_in[2];
    const float* sigmas = (const float*)d_in[3];
    const float* priors = (const float*)d_in[4];
    float* out = (float*)d_out;

    cudaFuncSetAttribute(nb_mma, cudaFuncAttributeMaxDynamicSharedMemorySize, SMEM_TOTAL);

    prep_B<<<NREL, 256>>>(mus, sigmas, priors);
    nb_mma<<<128, 512, SMEM_TOTAL>>>(sbjs, objs, out);
    (void)in_sizes; (void)n_in; (void)out_size;
}

// round 13
// speedup vs baseline: 1.1759x; 1.0490x over previous
#include <cuda_runtime.h>
#include <cuda_bf16.h>
#include <cstdint>

#define BATCH  4096
#define NREL   128
#define EMB    256
#define KDIM   512
#define NSEG   8          // 8 segments of 64 source floats; pair [x^2_seg, x_seg]

// ---------------- device globals ----------------
// B pre-packed: [2 ntiles][8 segs][ w2-tile 8K | w1-tile 8K ]  (256 KB)
__device__ __align__(128) __nv_bfloat16 g_Bs[NREL * 1024];
__device__ __align__(16) float g_const[NREL];

// ---------------- helpers ----------------
__device__ __forceinline__ uint32_t smem_u32(const void* p) {
    uint32_t a;
    asm("{ .reg .u64 t; cvta.to.shared.u64 t, %1; cvt.u32.u64 %0, t; }" : "=r"(a) : "l"(p));
    return a;
}
__device__ __forceinline__ void ldsm_x4(uint32_t& r0, uint32_t& r1, uint32_t& r2, uint32_t& r3,
                                        uint32_t addr) {
    asm volatile("ldmatrix.sync.aligned.m8n8.x4.shared.b16 {%0,%1,%2,%3}, [%4];"
                 : "=r"(r0), "=r"(r1), "=r"(r2), "=r"(r3) : "r"(addr));
}
__device__ __forceinline__ void mma16816(float* d, const uint32_t* a, uint32_t b0, uint32_t b1) {
    asm volatile(
        "mma.sync.aligned.m16n8k16.row.col.f32.bf16.bf16.f32 "
        "{%0,%1,%2,%3}, {%4,%5,%6,%7}, {%8,%9}, {%0,%1,%2,%3};"
        : "+f"(d[0]), "+f"(d[1]), "+f"(d[2]), "+f"(d[3])
        : "r"(a[0]), "r"(a[1]), "r"(a[2]), "r"(a[3]), "r"(b0), "r"(b1));
}
#define MBAR_INIT(addr, cnt) \
    asm volatile("mbarrier.init.shared.b64 [%0], %1;" :: "r"(addr), "r"((uint32_t)(cnt)) : "memory")
#define MBAR_EXPECT_TX(addr, bytes) \
    asm volatile("mbarrier.arrive.expect_tx.shared.b64 _, [%0], %1;" :: "r"(addr), "r"((uint32_t)(bytes)) : "memory")
#define MBAR_WAIT(addr, par) do { \
    uint32_t _m = (addr); uint32_t _p = (par); uint32_t _d; \
    asm volatile("{\n\t.reg .pred p;\n\tmbarrier.try_wait.parity.acquire.cta.shared::cta.b64 p, [%1], %2;\n\tselp.b32 %0, 1, 0, p;\n\t}" \
        : "=r"(_d) : "r"(_m), "r"(_p) : "memory"); \
    if (!_d) { \
        asm volatile("{\n\t.reg .pred P1;\n\tWL_%=: \n\tmbarrier.try_wait.parity.acquire.cta.shared::cta.b64 P1, [%0], %1, 0x989680;\n\t@P1 bra.uni WD_%=;\n\tbra.uni WL_%=;\n\tWD_%=: \n\t}" \
            :: "r"(_m), "r"(_p) : "memory"); \
    } } while (0)
#define CP_BULK(dst, src, sz, mbar) \
    asm volatile("cp.async.bulk.shared::cta.global.mbarrier::complete_tx::bytes [%0], [%1], %2, [%3];" \
        :: "r"(dst), "l"(src), "r"((uint32_t)(sz)), "r"(mbar) : "memory")

#define SWZ(bo) ((bo) ^ (((bo) >> 3) & 0x70))

// ---------------- prep: pack B + const (one block per relation) ----------------
__global__ void prep_B(const float* __restrict__ mus,
                       const float* __restrict__ sigmas,
                       const float* __restrict__ priors) {
    const int r = blockIdx.x;          // 0..127
    const int t = threadIdx.x;         // 0..255
    const int nt  = r >> 6;            // ntile
    const int rin = r & 63;
    char* base = reinterpret_cast<char*>(g_Bs) + (size_t)nt * 8 * 16384;

    float part = 0.0f;
    #pragma unroll
    for (int i = 0; i < 2; i++) {
        const int k = t + i * 256;     // 0..511
        const float s    = sigmas[r * KDIM + k];
        const float mu   = mus[r * KDIM + k];
        const float inv2 = 1.0f / (s * s);
        const int seg = k >> 6;
        const uint32_t off = SWZ((uint32_t)(rin * 128 + (k & 63) * 2));
        *reinterpret_cast<__nv_bfloat16*>(base + (size_t)seg * 16384 + off)
            = __float2bfloat16(-0.5f * inv2);        // w2 <-> x^2
        *reinterpret_cast<__nv_bfloat16*>(base + (size_t)seg * 16384 + 8192 + off)
            = __float2bfloat16(mu * inv2);           // w1 <-> x
        part += -0.5f * mu * mu * inv2 - logf(s) - 0.9189385332046727f;
    }

    __shared__ float red[8];
    #pragma unroll
    for (int off = 16; off > 0; off >>= 1)
        part += __shfl_down_sync(0xffffffffu, part, off);
    if ((t & 31) == 0) red[t >> 5] = part;
    __syncthreads();
    if (t < 8) {
        float v = red[t];
        #pragma unroll
        for (int off = 4; off > 0; off >>= 1)
            v += __shfl_down_sync(0x000000ffu, v, off);
        if (t == 0) g_const[r] = v + priors[r] * (float)KDIM;
    }
}

// ---------------- main ----------------
// CTA 64(m) x 64(n), 512 threads = 4 K-groups x 4 warps (warp tile 32x32).
// Group g computes segments {g, g+4}; 4 partials reduced in smem at the end.
//   A: per-group buffer [4][x^2 8K | x 8K] = 64 KB (LDG->STS, 2 rounds)
//   B: fully resident [8 segs][w2 8K | w1 8K] = 128 KB (bulk, 8 mbarriers)
#define SMB_OFF     65536
#define MBAR_OFF    (SMB_OFF + NSEG * 16384)     // 196608
#define SMEM_TOTAL  (MBAR_OFF + 64)              // 196672

__global__ __launch_bounds__(512)
void nb_mma(const float* __restrict__ sbjs,
            const float* __restrict__ objs,
            float* __restrict__ out) {
    extern __shared__ char smem[];
    const uint32_t sb = smem_u32(smem);

    const int tid   = threadIdx.x;
    const int lane  = tid & 31;
    const int wid   = tid >> 5;             // 0..15
    const int group = wid >> 2;             // 0..3 (one warp per SMSP per group)
    const int gw    = wid & 3;
    const int wm    = gw & 1;               // m offset 32
    const int wn    = gw >> 1;              // n offset 32
    const int gtid  = tid & 127;            // thread within group
    const int mtile = blockIdx.x >> 1;      // 0..63
    const int ntile = blockIdx.x & 1;       // 0..1

    if (tid == 0) {
        #pragma unroll
        for (int s = 0; s < NSEG; s++) MBAR_INIT(sb + MBAR_OFF + s * 8, 1);
    }
    __syncthreads();

    if (tid == 0) {
        const char* bSrc = reinterpret_cast<const char*>(g_Bs) + (size_t)ntile * 8 * 16384;
        #pragma unroll
        for (int s = 0; s < NSEG; s++) {
            const uint32_t mb = sb + MBAR_OFF + s * 8;
            MBAR_EXPECT_TX(mb, 16384);
            CP_BULK(sb + SMB_OFF + s * 16384, bSrc + (size_t)s * 16384, 16384, mb);
        }
    }

    // ---- per-group A loader (128 threads, 4 virtual passes of R12 mapping) ----
    auto ldgA = [&](int seg, float4* v) {
        #pragma unroll
        for (int p = 0; p < 4; p++) {
            const int vt   = gtid + p * 128;     // 0..511
            const int arow = vt >> 3;            // 0..63
            const int kq   = (vt & 7) * 8;       // 0..56
            const int kg   = seg * 64 + kq;
            const float* src = (kg < EMB)
                ? sbjs + (size_t)(mtile * 64 + arow) * EMB + kg
                : objs + (size_t)(mtile * 64 + arow) * EMB + (kg - EMB);
            v[2 * p]     = reinterpret_cast<const float4*>(src)[0];
            v[2 * p + 1] = reinterpret_cast<const float4*>(src)[1];
        }
    };
    auto stsA = [&](const float4* v) {
        char* dst = smem + (size_t)group * 16384;
        #pragma unroll
        for (int p = 0; p < 4; p++) {
            const int vt   = gtid + p * 128;
            const int arow = vt >> 3;
            const int kq   = (vt & 7) * 8;
            const uint32_t aOff = SWZ((uint32_t)(arow * 128 + kq * 2));
            const float4 v0 = v[2 * p], v1 = v[2 * p + 1];
            __nv_bfloat162 q0 = __floats2bfloat162_rn(v0.x * v0.x, v0.y * v0.y);
            __nv_bfloat162 q1 = __floats2bfloat162_rn(v0.z * v0.z, v0.w * v0.w);
            __nv_bfloat162 q2 = __floats2bfloat162_rn(v1.x * v1.x, v1.y * v1.y);
            __nv_bfloat162 q3 = __floats2bfloat162_rn(v1.z * v1.z, v1.w * v1.w);
            __nv_bfloat162 r0 = __floats2bfloat162_rn(v0.x, v0.y);
            __nv_bfloat162 r1 = __floats2bfloat162_rn(v0.z, v0.w);
            __nv_bfloat162 r2 = __floats2bfloat162_rn(v1.x, v1.y);
            __nv_bfloat162 r3 = __floats2bfloat162_rn(v1.z, v1.w);
            uint4 uq, ur;
            uq.x = *reinterpret_cast<uint32_t*>(&q0); uq.y = *reinterpret_cast<uint32_t*>(&q1);
            uq.z = *reinterpret_cast<uint32_t*>(&q2); uq.w = *reinterpret_cast<uint32_t*>(&q3);
            ur.x = *reinterpret_cast<uint32_t*>(&r0); ur.y = *reinterpret_cast<uint32_t*>(&r1);
            ur.z = *reinterpret_cast<uint32_t*>(&r2); ur.w = *reinterpret_cast<uint32_t*>(&r3);
            *reinterpret_cast<uint4*>(dst + aOff)        = uq;   // x^2 tile
            *reinterpret_cast<uint4*>(dst + 8192 + aOff) = ur;   // x tile
        }
    };
    #define BARG() asm volatile("bar.sync %0, %1;" :: "r"(group + 1), "r"(128) : "memory")

    // ---- compute mappings: warp tile 32x32 = 2 m-frags x 2 B-ldsm (4 n8-frags) ----
    uint32_t aRowOff[2], aXorr[2];
    #pragma unroll
    for (int mf = 0; mf < 2; mf++) {
        const int row = wm * 32 + mf * 16 + (lane & 15);
        aRowOff[mf] = (uint32_t)(row * 128);
        aXorr[mf]   = (uint32_t)((row & 7) << 4);
    }
    const uint32_t aBlk = (uint32_t)((lane >> 4) * 16);
    uint32_t bRowOff[2], bXorr[2];
    #pragma unroll
    for (int bf = 0; bf < 2; bf++) {
        const int nrow = wn * 32 + bf * 16 + ((lane >> 4) * 8) + (lane & 7);
        bRowOff[bf] = (uint32_t)(nrow * 128);
        bXorr[bf]   = (uint32_t)((nrow & 7) << 4);
    }
    const uint32_t bBlk = (uint32_t)(((lane >> 3) & 1) * 16);

    float acc[2][4][4];
    #pragma unroll
    for (int i = 0; i < 2; i++)
        #pragma unroll
        for (int j = 0; j < 4; j++)
            #pragma unroll
            for (int k = 0; k < 4; k++) acc[i][j][k] = 0.0f;

    auto compute_seg = [&](int seg) {
        const uint32_t aStage = sb + (uint32_t)group * 16384;
        const uint32_t bStage = sb + SMB_OFF + (uint32_t)seg * 16384;
        #pragma unroll
        for (int kc = 0; kc < 2; kc++) {            // kc=0: x^2*w2, kc=1: x*w1
            const uint32_t aB = aStage + kc * 8192;
            const uint32_t bB = bStage + kc * 8192;
            #pragma unroll
            for (int ks = 0; ks < 4; ks++) {
                const uint32_t kcol = (uint32_t)(ks * 32);
                uint32_t a0[4], a1[4], b0[4], b1[4];
                ldsm_x4(a0[0], a0[1], a0[2], a0[3], aB + aRowOff[0] + ((kcol + aBlk) ^ aXorr[0]));
                ldsm_x4(a1[0], a1[1], a1[2], a1[3], aB + aRowOff[1] + ((kcol + aBlk) ^ aXorr[1]));
                ldsm_x4(b0[0], b0[1], b0[2], b0[3], bB + bRowOff[0] + ((kcol + bBlk) ^ bXorr[0]));
                ldsm_x4(b1[0], b1[1], b1[2], b1[3], bB + bRowOff[1] + ((kcol + bBlk) ^ bXorr[1]));
                mma16816(acc[0][0], a0, b0[0], b0[1]);
                mma16816(acc[0][1], a0, b0[2], b0[3]);
                mma16816(acc[0][2], a0, b1[0], b1[1]);
                mma16816(acc[0][3], a0, b1[2], b1[3]);
                mma16816(acc[1][0], a1, b0[0], b0[1]);
                mma16816(acc[1][1], a1, b0[2], b0[3]);
                mma16816(acc[1][2], a1, b1[0], b1[1]);
                mma16816(acc[1][3], a1, b1[2], b1[3]);
            }
        }
    };

    // ---- group flow: seg = group, then seg = group + 4 ----
    float4 v[8];
    ldgA(group, v);
    stsA(v);
    BARG();
    MBAR_WAIT(sb + MBAR_OFF + group * 8, 0);
    compute_seg(group);
    ldgA(group + 4, v);          // LDG latency overlaps the barrier wait below
    BARG();
    stsA(v);
    BARG();
    MBAR_WAIT(sb + MBAR_OFF + (group + 4) * 8, 0);
    compute_seg(group + 4);
    BARG();

    // ---- partials -> smem (each group overwrites its own A region) ----
    {
        float* red = reinterpret_cast<float*>(smem + (size_t)group * 16384);
        #pragma unroll
        for (int mf = 0; mf < 2; mf++) {
            #pragma unroll
            for (int nf = 0; nf < 4; nf++) {
                const int row0 = wm * 32 + mf * 16 + (lane >> 2);
                const int col0 = wn * 32 + nf * 8 + (lane & 3) * 2;
                float2 lo, hi;
                lo.x = acc[mf][nf][0]; lo.y = acc[mf][nf][1];
                hi.x = acc[mf][nf][2]; hi.y = acc[mf][nf][3];
                *reinterpret_cast<float2*>(&red[row0 * 64 + col0])       = lo;
                *reinterpret_cast<float2*>(&red[(row0 + 8) * 64 + col0]) = hi;
            }
        }
    }
    __syncthreads();

    // ---- reduce 4 partials + const -> global ----
    {
        const int row = tid >> 3;            // 0..63
        const int c8  = (tid & 7) * 8;       // 0..56
        float4 s0 = make_float4(0.f, 0.f, 0.f, 0.f);
        float4 s1 = make_float4(0.f, 0.f, 0.f, 0.f);
        #pragma unroll
        for (int g = 0; g < 4; g++) {
            const float* rg = reinterpret_cast<const float*>(smem + (size_t)g * 16384);
            const float4 f0 = *reinterpret_cast<const float4*>(&rg[row * 64 + c8]);
            const float4 f1 = *reinterpret_cast<const float4*>(&rg[row * 64 + c8 + 4]);
            s0.x += f0.x; s0.y += f0.y; s0.z += f0.z; s0.w += f0.w;
            s1.x += f1.x; s1.y += f1.y; s1.z += f1.z; s1.w += f1.w;
        }
        const float4 c0 = *reinterpret_cast<const float4*>(&g_const[ntile * 64 + c8]);
        const float4 c1 = *reinterpret_cast<const float4*>(&g_const[ntile * 64 + c8 + 4]);
        s0.x += c0.x; s0.y += c0.y; s0.z += c0.z; s0.w += c0.w;
        s1.x += c1.x; s1.y += c1.y; s1.z += c1.z; s1.w += c1.w;
        float* o = &out[(size_t)(mtile * 64 + row) * NREL + ntile * 64 + c8];
        reinterpret_cast<float4*>(o)[0] = s0;
        reinterpret_cast<float4*>(o)[1] = s1;
    }
}

extern "C" void kernel_launch(void* const* d_in, const int* in_sizes, int n_in,
                              void* d_out, int out_size) {
    const float* sbjs   = (const float*)d_in[0];
    const float* objs   = (const float*)d_in[1];
    const float* mus    = (const float*)d_in[2];
    const float* sigmas = (const float*)d_in[3];
    const float* priors = (const float*)d_in[4];
    float* out = (float*)d_out;

    cudaFuncSetAttribute(nb_mma, cudaFuncAttributeMaxDynamicSharedMemorySize, SMEM_TOTAL);

    prep_B<<<NREL, 256>>>(mus, sigmas, priors);
    nb_mma<<<128, 512, SMEM_TOTAL>>>(sbjs, objs, out);
    (void)in_sizes; (void)n_in; (void)out_size;
}

// round 14
// speedup vs baseline: 1.2973x; 1.1032x over previous
#include <cuda_runtime.h>
#include <cuda_bf16.h>
#include <cstdint>

#define BATCH  4096
#define NREL   128
#define EMB    256
#define KDIM   512
#define NSEG   8          // 8 segments of 64 source floats; pair [x^2_seg, x_seg]

// ---------------- device globals ----------------
// B pre-packed: [2 ntiles][8 segs][ w2-tile 8K | w1-tile 8K ]  (256 KB)
__device__ __align__(128) __nv_bfloat16 g_Bs[NREL * 1024];
__device__ __align__(16) float g_const[NREL];

// ---------------- helpers ----------------
__device__ __forceinline__ uint32_t smem_u32(const void* p) {
    uint32_t a;
    asm("{ .reg .u64 t; cvta.to.shared.u64 t, %1; cvt.u32.u64 %0, t; }" : "=r"(a) : "l"(p));
    return a;
}
__device__ __forceinline__ void ldsm_x4(uint32_t& r0, uint32_t& r1, uint32_t& r2, uint32_t& r3,
                                        uint32_t addr) {
    asm volatile("ldmatrix.sync.aligned.m8n8.x4.shared.b16 {%0,%1,%2,%3}, [%4];"
                 : "=r"(r0), "=r"(r1), "=r"(r2), "=r"(r3) : "r"(addr));
}
__device__ __forceinline__ void mma16816(float* d, const uint32_t* a, uint32_t b0, uint32_t b1) {
    asm volatile(
        "mma.sync.aligned.m16n8k16.row.col.f32.bf16.bf16.f32 "
        "{%0,%1,%2,%3}, {%4,%5,%6,%7}, {%8,%9}, {%0,%1,%2,%3};"
        : "+f"(d[0]), "+f"(d[1]), "+f"(d[2]), "+f"(d[3])
        : "r"(a[0]), "r"(a[1]), "r"(a[2]), "r"(a[3]), "r"(b0), "r"(b1));
}
#define MBAR_INIT(addr, cnt) \
    asm volatile("mbarrier.init.shared.b64 [%0], %1;" :: "r"(addr), "r"((uint32_t)(cnt)) : "memory")
#define MBAR_EXPECT_TX(addr, bytes) \
    asm volatile("mbarrier.arrive.expect_tx.shared.b64 _, [%0], %1;" :: "r"(addr), "r"((uint32_t)(bytes)) : "memory")
#define MBAR_WAIT(addr, par) do { \
    uint32_t _m = (addr); uint32_t _p = (par); uint32_t _d; \
    asm volatile("{\n\t.reg .pred p;\n\tmbarrier.try_wait.parity.acquire.cta.shared::cta.b64 p, [%1], %2;\n\tselp.b32 %0, 1, 0, p;\n\t}" \
        : "=r"(_d) : "r"(_m), "r"(_p) : "memory"); \
    if (!_d) { \
        asm volatile("{\n\t.reg .pred P1;\n\tWL_%=: \n\tmbarrier.try_wait.parity.acquire.cta.shared::cta.b64 P1, [%0], %1, 0x989680;\n\t@P1 bra.uni WD_%=;\n\tbra.uni WL_%=;\n\tWD_%=: \n\t}" \
            :: "r"(_m), "r"(_p) : "memory"); \
    } } while (0)
#define CP_BULK(dst, src, sz, mbar) \
    asm volatile("cp.async.bulk.shared::cta.global.mbarrier::complete_tx::bytes [%0], [%1], %2, [%3];" \
        :: "r"(dst), "l"(src), "r"((uint32_t)(sz)), "r"(mbar) : "memory")

#define SWZ(bo) ((bo) ^ (((bo) >> 3) & 0x70))

// ---------------- prep: pack B + const (one block per relation) ----------------
__global__ void prep_B(const float* __restrict__ mus,
                       const float* __restrict__ sigmas,
                       const float* __restrict__ priors) {
    // PDL: release the dependent grid immediately; its prologue (A loads,
    // mbar init) overlaps this kernel. Consumers gate on griddepcontrol.wait.
    asm volatile("griddepcontrol.launch_dependents;");

    const int r = blockIdx.x;          // 0..127
    const int t = threadIdx.x;         // 0..255
    const int nt  = r >> 6;            // ntile
    const int rin = r & 63;
    char* base = reinterpret_cast<char*>(g_Bs) + (size_t)nt * 8 * 16384;

    float part = 0.0f;
    #pragma unroll
    for (int i = 0; i < 2; i++) {
        const int k = t + i * 256;     // 0..511
        const float s    = sigmas[r * KDIM + k];
        const float mu   = mus[r * KDIM + k];
        const float inv2 = 1.0f / (s * s);
        const int seg = k >> 6;
        const uint32_t off = SWZ((uint32_t)(rin * 128 + (k & 63) * 2));
        *reinterpret_cast<__nv_bfloat16*>(base + (size_t)seg * 16384 + off)
            = __float2bfloat16(-0.5f * inv2);        // w2 <-> x^2
        *reinterpret_cast<__nv_bfloat16*>(base + (size_t)seg * 16384 + 8192 + off)
            = __float2bfloat16(mu * inv2);           // w1 <-> x
        part += -0.5f * mu * mu * inv2 - logf(s) - 0.9189385332046727f;
    }

    __shared__ float red[8];
    #pragma unroll
    for (int off = 16; off > 0; off >>= 1)
        part += __shfl_down_sync(0xffffffffu, part, off);
    if ((t & 31) == 0) red[t >> 5] = part;
    __syncthreads();
    if (t < 8) {
        float v = red[t];
        #pragma unroll
        for (int off = 4; off > 0; off >>= 1)
            v += __shfl_down_sync(0x000000ffu, v, off);
        if (t == 0) g_const[r] = v + priors[r] * (float)KDIM;
    }
}

// ---------------- main ----------------
// CTA 64(m) x 64(n), 512 threads = 4 K-groups x 4 warps (warp tile 32x32).
// Group g computes segments {g, g+4}; 4 partials reduced in smem at the end.
//   A: per-group buffer [4][x^2 8K | x 8K] = 64 KB (LDG->STS, 2 rounds)
//   B: fully resident [8 segs][w2 8K | w1 8K] = 128 KB (bulk, 8 mbarriers)
#define SMB_OFF     65536
#define MBAR_OFF    (SMB_OFF + NSEG * 16384)     // 196608
#define SMEM_TOTAL  (MBAR_OFF + 64)              // 196672

__global__ __launch_bounds__(512)
void nb_mma(const float* __restrict__ sbjs,
            const float* __restrict__ objs,
            float* __restrict__ out) {
    extern __shared__ char smem[];
    const uint32_t sb = smem_u32(smem);

    const int tid   = threadIdx.x;
    const int lane  = tid & 31;
    const int wid   = tid >> 5;             // 0..15
    const int group = wid >> 2;             // 0..3 (one warp per SMSP per group)
    const int gw    = wid & 3;
    const int wm    = gw & 1;               // m offset 32
    const int wn    = gw >> 1;              // n offset 32
    const int gtid  = tid & 127;            // thread within group
    const int mtile = blockIdx.x >> 1;      // 0..63
    const int ntile = blockIdx.x & 1;       // 0..1

    if (tid == 0) {
        #pragma unroll
        for (int s = 0; s < NSEG; s++) MBAR_INIT(sb + MBAR_OFF + s * 8, 1);
    }
    __syncthreads();

    // B bulk issue gated on prep_B completion; done from group 3 (computes last)
    // so the wait is maximally hidden behind groups 0-2's A loads.
    if (tid == 384) {
        asm volatile("griddepcontrol.wait;");
        const char* bSrc = reinterpret_cast<const char*>(g_Bs) + (size_t)ntile * 8 * 16384;
        #pragma unroll
        for (int s = 0; s < NSEG; s++) {
            const uint32_t mb = sb + MBAR_OFF + s * 8;
            MBAR_EXPECT_TX(mb, 16384);
            CP_BULK(sb + SMB_OFF + s * 16384, bSrc + (size_t)s * 16384, 16384, mb);
        }
    }

    // ---- per-group A loader (128 threads, 4 virtual passes) ----
    auto ldgA = [&](int seg, float4* v) {
        #pragma unroll
        for (int p = 0; p < 4; p++) {
            const int vt   = gtid + p * 128;     // 0..511
            const int arow = vt >> 3;            // 0..63
            const int kq   = (vt & 7) * 8;       // 0..56
            const int kg   = seg * 64 + kq;
            const float* src = (kg < EMB)
                ? sbjs + (size_t)(mtile * 64 + arow) * EMB + kg
                : objs + (size_t)(mtile * 64 + arow) * EMB + (kg - EMB);
            v[2 * p]     = reinterpret_cast<const float4*>(src)[0];
            v[2 * p + 1] = reinterpret_cast<const float4*>(src)[1];
        }
    };
    auto stsA = [&](const float4* v) {
        char* dst = smem + (size_t)group * 16384;
        #pragma unroll
        for (int p = 0; p < 4; p++) {
            const int vt   = gtid + p * 128;
            const int arow = vt >> 3;
            const int kq   = (vt & 7) * 8;
            const uint32_t aOff = SWZ((uint32_t)(arow * 128 + kq * 2));
            const float4 v0 = v[2 * p], v1 = v[2 * p + 1];
            __nv_bfloat162 q0 = __floats2bfloat162_rn(v0.x * v0.x, v0.y * v0.y);
            __nv_bfloat162 q1 = __floats2bfloat162_rn(v0.z * v0.z, v0.w * v0.w);
            __nv_bfloat162 q2 = __floats2bfloat162_rn(v1.x * v1.x, v1.y * v1.y);
            __nv_bfloat162 q3 = __floats2bfloat162_rn(v1.z * v1.z, v1.w * v1.w);
            __nv_bfloat162 r0 = __floats2bfloat162_rn(v0.x, v0.y);
            __nv_bfloat162 r1 = __floats2bfloat162_rn(v0.z, v0.w);
            __nv_bfloat162 r2 = __floats2bfloat162_rn(v1.x, v1.y);
            __nv_bfloat162 r3 = __floats2bfloat162_rn(v1.z, v1.w);
            uint4 uq, ur;
            uq.x = *reinterpret_cast<uint32_t*>(&q0); uq.y = *reinterpret_cast<uint32_t*>(&q1);
            uq.z = *reinterpret_cast<uint32_t*>(&q2); uq.w = *reinterpret_cast<uint32_t*>(&q3);
            ur.x = *reinterpret_cast<uint32_t*>(&r0); ur.y = *reinterpret_cast<uint32_t*>(&r1);
            ur.z = *reinterpret_cast<uint32_t*>(&r2); ur.w = *reinterpret_cast<uint32_t*>(&r3);
            *reinterpret_cast<uint4*>(dst + aOff)        = uq;   // x^2 tile
            *reinterpret_cast<uint4*>(dst + 8192 + aOff) = ur;   // x tile
        }
    };
    #define BARG() asm volatile("bar.sync %0, %1;" :: "r"(group + 1), "r"(128) : "memory")

    // ---- compute mappings: warp tile 32x32 = 2 m-frags x 2 B-ldsm ----
    uint32_t aRowOff[2], aXorr[2];
    #pragma unroll
    for (int mf = 0; mf < 2; mf++) {
        const int row = wm * 32 + mf * 16 + (lane & 15);
        aRowOff[mf] = (uint32_t)(row * 128);
        aXorr[mf]   = (uint32_t)((row & 7) << 4);
    }
    const uint32_t aBlk = (uint32_t)((lane >> 4) * 16);
    uint32_t bRowOff[2], bXorr[2];
    #pragma unroll
    for (int bf = 0; bf < 2; bf++) {
        const int nrow = wn * 32 + bf * 16 + ((lane >> 4) * 8) + (lane & 7);
        bRowOff[bf] = (uint32_t)(nrow * 128);
        bXorr[bf]   = (uint32_t)((nrow & 7) << 4);
    }
    const uint32_t bBlk = (uint32_t)(((lane >> 3) & 1) * 16);

    float acc[2][4][4];
    #pragma unroll
    for (int i = 0; i < 2; i++)
        #pragma unroll
        for (int j = 0; j < 4; j++)
            #pragma unroll
            for (int k = 0; k < 4; k++) acc[i][j][k] = 0.0f;

    auto compute_seg = [&](int seg) {
        const uint32_t aStage = sb + (uint32_t)group * 16384;
        const uint32_t bStage = sb + SMB_OFF + (uint32_t)seg * 16384;
        #pragma unroll
        for (int kc = 0; kc < 2; kc++) {            // kc=0: x^2*w2, kc=1: x*w1
            const uint32_t aB = aStage + kc * 8192;
            const uint32_t bB = bStage + kc * 8192;
            #pragma unroll
            for (int ks = 0; ks < 4; ks++) {
                const uint32_t kcol = (uint32_t)(ks * 32);
                uint32_t a0[4], a1[4], b0[4], b1[4];
                ldsm_x4(a0[0], a0[1], a0[2], a0[3], aB + aRowOff[0] + ((kcol + aBlk) ^ aXorr[0]));
                ldsm_x4(a1[0], a1[1], a1[2], a1[3], aB + aRowOff[1] + ((kcol + aBlk) ^ aXorr[1]));
                ldsm_x4(b0[0], b0[1], b0[2], b0[3], bB + bRowOff[0] + ((kcol + bBlk) ^ bXorr[0]));
                ldsm_x4(b1[0], b1[1], b1[2], b1[3], bB + bRowOff[1] + ((kcol + bBlk) ^ bXorr[1]));
                mma16816(acc[0][0], a0, b0[0], b0[1]);
                mma16816(acc[0][1], a0, b0[2], b0[3]);
                mma16816(acc[0][2], a0, b1[0], b1[1]);
                mma16816(acc[0][3], a0, b1[2], b1[3]);
                mma16816(acc[1][0], a1, b0[0], b0[1]);
                mma16816(acc[1][1], a1, b0[2], b0[3]);
                mma16816(acc[1][2], a1, b1[0], b1[1]);
                mma16816(acc[1][3], a1, b1[2], b1[3]);
            }
        }
    };

    // ---- group flow: seg = group, then seg = group + 4 ----
    float4 v[8];
    ldgA(group, v);
    stsA(v);
    BARG();
    MBAR_WAIT(sb + MBAR_OFF + group * 8, 0);
    compute_seg(group);
    ldgA(group + 4, v);          // LDG latency overlaps the barrier wait below
    BARG();
    stsA(v);
    BARG();
    MBAR_WAIT(sb + MBAR_OFF + (group + 4) * 8, 0);
    compute_seg(group + 4);
    BARG();

    // ---- partials -> smem (each group overwrites its own A region) ----
    {
        float* red = reinterpret_cast<float*>(smem + (size_t)group * 16384);
        #pragma unroll
        for (int mf = 0; mf < 2; mf++) {
            #pragma unroll
            for (int nf = 0; nf < 4; nf++) {
                const int row0 = wm * 32 + mf * 16 + (lane >> 2);
                const int col0 = wn * 32 + nf * 8 + (lane & 3) * 2;
                float2 lo, hi;
                lo.x = acc[mf][nf][0]; lo.y = acc[mf][nf][1];
                hi.x = acc[mf][nf][2]; hi.y = acc[mf][nf][3];
                *reinterpret_cast<float2*>(&red[row0 * 64 + col0])       = lo;
                *reinterpret_cast<float2*>(&red[(row0 + 8) * 64 + col0]) = hi;
            }
        }
    }
    __syncthreads();

    // ---- reduce 4 partials + const -> global ----
    {
        const int row = tid >> 3;            // 0..63
        const int c8  = (tid & 7) * 8;       // 0..56
        float4 s0 = make_float4(0.f, 0.f, 0.f, 0.f);
        float4 s1 = make_float4(0.f, 0.f, 0.f, 0.f);
        #pragma unroll
        for (int g = 0; g < 4; g++) {
            const float* rg = reinterpret_cast<const float*>(smem + (size_t)g * 16384);
            const float4 f0 = *reinterpret_cast<const float4*>(&rg[row * 64 + c8]);
            const float4 f1 = *reinterpret_cast<const float4*>(&rg[row * 64 + c8 + 4]);
            s0.x += f0.x; s0.y += f0.y; s0.z += f0.z; s0.w += f0.w;
            s1.x += f1.x; s1.y += f1.y; s1.z += f1.z; s1.w += f1.w;
        }
        const float4 c0 = *reinterpret_cast<const float4*>(&g_const[ntile * 64 + c8]);
        const float4 c1 = *reinterpret_cast<const float4*>(&g_const[ntile * 64 + c8 + 4]);
        s0.x += c0.x; s0.y += c0.y; s0.z += c0.z; s0.w += c0.w;
        s1.x += c1.x; s1.y += c1.y; s1.z += c1.z; s1.w += c1.w;
        float* o = &out[(size_t)(mtile * 64 + row) * NREL + ntile * 64 + c8];
        reinterpret_cast<float4*>(o)[0] = s0;
        reinterpret_cast<float4*>(o)[1] = s1;
    }
}

extern "C" void kernel_launch(void* const* d_in, const int* in_sizes, int n_in,
                              void* d_out, int out_size) {
    const float* sbjs   = (const float*)d_in[0];
    const float* objs   = (const float*)d_in[1];
    const float* mus    = (const float*)d_in[2];
    const float* sigmas = (const float*)d_in[3];
    const float* priors = (const float*)d_in[4];
    float* out = (float*)d_out;

    cudaFuncSetAttribute(nb_mma, cudaFuncAttributeMaxDynamicSharedMemorySize, SMEM_TOTAL);

    prep_B<<<NREL, 256>>>(mus, sigmas, priors);

    // PDL launch: nb_mma may start while prep_B runs; its B consumers gate on
    // griddepcontrol.wait. Fall back to a plain launch if PDL is unavailable
    // (griddepcontrol.wait is a no-op without the programmatic edge).
    cudaLaunchConfig_t cfg = {};
    cfg.gridDim  = dim3(128, 1, 1);
    cfg.blockDim = dim3(512, 1, 1);
    cfg.dynamicSmemBytes = SMEM_TOTAL;
    cfg.stream = 0;
    cudaLaunchAttribute attrs[1];
    attrs[0].id = cudaLaunchAttributeProgrammaticStreamSerialization;
    attrs[0].val.programmaticStreamSerializationAllowed = 1;
    cfg.attrs = attrs;
    cfg.numAttrs = 1;
    cudaError_t e = cudaLaunchKernelEx(&cfg, nb_mma, sbjs, objs, out);
    if (e != cudaSuccess) {
        (void)cudaGetLastError();   // clear sticky error
        nb_mma<<<128, 512, SMEM_TOTAL>>>(sbjs, objs, out);
    }
    (void)in_sizes; (void)n_in; (void)out_size;
}